// round 10
// baseline (speedup 1.0000x reference)
#include <cuda_runtime.h>
#include <math.h>

// ---------------------------------------------------------------------------
// Problem dims
// ---------------------------------------------------------------------------
#define NBLK   148
#define NTHR   256
#define GSTRIDE (NBLK * NTHR)
#define Bz     128
#define Sz     512
#define Hz     1024
#define MIDz   512
#define FEATz  576
#define G4Hz   4096
#define KC     16

// Output layout: outs[B,S,H], h2f[1,B,H], c2f[1,B,H], flags[S]
#define OUT_H2    67108864
#define OUT_C2    67239936
#define OUT_FLAGS 67371008

typedef unsigned long long ull;

// ---------------------------------------------------------------------------
// Device-global scratch (allocation-free per harness rules)
// ---------------------------------------------------------------------------
__device__ __align__(16) float g_embeds[(size_t)Sz * Bz * FEATz];   // [t][b][f]
__device__ __align__(16) float g_mx1all[(size_t)Sz * Bz * Hz];      // X@Wmx1^T
__device__ __align__(16) float g_zx1all[(size_t)Sz * Bz * G4Hz];    // X@Wih1^T
__device__ __align__(16) float g_zbxv[Sz * Bz];                     // x·u + bdvs
__device__ __align__(16) float g_u[FEATz];                          // Wsi^T vs
__device__ __align__(16) float g_wv[Hz];                            // Wsh^T vs
__device__ float g_bdvs;

__device__ __align__(16) float g_h1[Bz * Hz];
__device__ __align__(16) float g_c1[Bz * Hz];
__device__ __align__(16) float g_h2[Bz * Hz];
__device__ __align__(16) float g_c2[Bz * Hz];
__device__ __align__(16) float g_x2[Bz * Hz];
__device__ __align__(16) float g_mh1p[2][Bz * Hz];
__device__ __align__(16) float g_p1p[2][Bz * G4Hz];
__device__ __align__(16) float g_mx2p[3][Bz * Hz];
__device__ __align__(16) float g_mh2p[3][Bz * Hz];
__device__ __align__(16) float g_zx2p[3][Bz * G4Hz];
__device__ __align__(16) float g_p2p[2][Bz * G4Hz];
__device__ __align__(16) float g_s[Bz];

// grid barrier state (zero-init; gen compared relatively, replay-safe)
__device__ unsigned g_bar_cnt;
__device__ volatile unsigned g_bar_gen;

__device__ __forceinline__ void gridbar() {
    __threadfence();               // release (emits CCTL.IVALL: scope >= cluster)
    __syncthreads();
    if (threadIdx.x == 0) {
        unsigned gen = g_bar_gen;
        if (atomicAdd(&g_bar_cnt, 1u) == (unsigned)(NBLK - 1)) {
            g_bar_cnt = 0u;
            __threadfence();
            g_bar_gen = gen + 1u;
        } else {
            while (g_bar_gen == gen) { __nanosleep(32); }
        }
    }
    __syncthreads();
    __threadfence();               // acquire: flush L1D so plain loads see fresh data
}

// ---------------------------------------------------------------------------
// Packed f32x2 FMA helpers (Blackwell; PTX required — ptxas won't auto-fuse)
// ---------------------------------------------------------------------------
__device__ __forceinline__ void ffma2(ull &acc, ull a, ull b) {
    asm("fma.rn.f32x2 %0, %1, %2, %0;" : "+l"(acc) : "l"(a), "l"(b));
}
__device__ __forceinline__ ull packdup(float x) {
    unsigned int u = __float_as_uint(x);
    ull r;
    asm("mov.b64 %0, {%1, %1};" : "=l"(r) : "r"(u));
    return r;
}
__device__ __forceinline__ float sigm(float x) { return 1.0f / (1.0f + expf(-x)); }

// ---------------------------------------------------------------------------
// Register-tiled fp32 GEMM tile: C[0:MROWS, 0:64] = A[MROWS,K] @ W[0:64,K]^T
//   A-operand = (sum_{j<NA} Ap[j]) * (NM ? sum_{j<NM} Mp[j] : 1)
// 256 threads. Double-buffered smem, ONE __syncthreads per KC chunk.
// MROWS in {128, 64}.
// ---------------------------------------------------------------------------
template<int MROWS, int NA, int NM>
__device__ __forceinline__ void gemm_tile(
    const float* const* Ap, const float* const* Mp, int lda,
    const float* __restrict__ W, int ldw, int K,
    float* __restrict__ C, int ldc,
    float (*As)[KC][130], float (*Ws)[KC][68])
{
    constexpr int NP = MROWS / 64;           // row-pairs per thread (2 or 1)
    const int tid = threadIdx.x;
    const int tx8 = (tid & 7) * 8;
    const int tyr = (tid >> 3) * (2 * NP);

    ull acc[NP][8];
#pragma unroll
    for (int i = 0; i < NP; i++)
#pragma unroll
        for (int j = 0; j < 8; j++) acc[i][j] = 0ull;

    float4 arA[NP][NA];
    float4 arM[NP][(NM > 0) ? NM : 1];
    float4 wr;

    auto loadA = [&](int k0) {
#pragma unroll
        for (int i = 0; i < NP; i++) {
            int id = i * 256 + tid;
            int r = id >> 2, kq = (id & 3) * 4;
            size_t off = (size_t)r * lda + k0 + kq;
#pragma unroll
            for (int j = 0; j < NA; j++) arA[i][j] = *(const float4*)(Ap[j] + off);
            if constexpr (NM > 0) {
#pragma unroll
                for (int j = 0; j < NM; j++) arM[i][j] = *(const float4*)(Mp[j] + off);
            }
        }
    };
    auto loadW = [&](int k0) {
        int r = tid >> 2, kq = (tid & 3) * 4;
        wr = *(const float4*)(W + (size_t)r * ldw + k0 + kq);
    };

    loadA(0); loadW(0);

    const int nc = K / KC;
    int buf = 0;
    for (int c = 0; c < nc; c++) {
        // stage regs -> smem[buf]
#pragma unroll
        for (int i = 0; i < NP; i++) {
            float4 v = arA[i][0];
#pragma unroll
            for (int j = 1; j < NA; j++) {
                v.x += arA[i][j].x; v.y += arA[i][j].y;
                v.z += arA[i][j].z; v.w += arA[i][j].w;
            }
            if constexpr (NM > 0) {
                float4 m = arM[i][0];
#pragma unroll
                for (int j = 1; j < NM; j++) {
                    m.x += arM[i][j].x; m.y += arM[i][j].y;
                    m.z += arM[i][j].z; m.w += arM[i][j].w;
                }
                v.x *= m.x; v.y *= m.y; v.z *= m.z; v.w *= m.w;
            }
            int id = i * 256 + tid;
            int r = id >> 2, kq = (id & 3) * 4;
            As[buf][kq + 0][r] = v.x; As[buf][kq + 1][r] = v.y;
            As[buf][kq + 2][r] = v.z; As[buf][kq + 3][r] = v.w;
        }
        {
            int r = tid >> 2, kq = (tid & 3) * 4;
            Ws[buf][kq + 0][r] = wr.x; Ws[buf][kq + 1][r] = wr.y;
            Ws[buf][kq + 2][r] = wr.z; Ws[buf][kq + 3][r] = wr.w;
        }
        __syncthreads();

        if (c + 1 < nc) { loadA((c + 1) * KC); loadW((c + 1) * KC); }  // prefetch

#pragma unroll
        for (int k = 0; k < KC; k++) {
            ull a2[NP];
#pragma unroll
            for (int i = 0; i < NP; i++)
                a2[i] = *(const ull*)&As[buf][k][tyr + 2 * i];
            float4 b0 = *(const float4*)&Ws[buf][k][tx8];
            float4 b1 = *(const float4*)&Ws[buf][k][tx8 + 4];
            ull bb[8];
            bb[0] = packdup(b0.x); bb[1] = packdup(b0.y);
            bb[2] = packdup(b0.z); bb[3] = packdup(b0.w);
            bb[4] = packdup(b1.x); bb[5] = packdup(b1.y);
            bb[6] = packdup(b1.z); bb[7] = packdup(b1.w);
#pragma unroll
            for (int i = 0; i < NP; i++)
#pragma unroll
                for (int j = 0; j < 8; j++) ffma2(acc[i][j], a2[i], bb[j]);
        }
        buf ^= 1;
    }
    __syncthreads();   // protect smem reuse by the block's next gemm_tile call

    // epilogue
#pragma unroll
    for (int i = 0; i < NP; i++) {
        int m = tyr + i * 2;
#pragma unroll
        for (int j = 0; j < 8; j++) {
            float lo = __uint_as_float((unsigned int)(acc[i][j] & 0xffffffffull));
            float hi = __uint_as_float((unsigned int)(acc[i][j] >> 32));
            C[(size_t)m * ldc + tx8 + j]       = lo;
            C[(size_t)(m + 1) * ldc + tx8 + j] = hi;
        }
    }
}

// ---------------------------------------------------------------------------
// The persistent kernel
// ---------------------------------------------------------------------------
__global__ __launch_bounds__(NTHR, 1) void enc_persistent(
    const int* __restrict__ ids, const int* __restrict__ xids,
    const float* __restrict__ wemb, const float* __restrict__ xemb,
    const float* __restrict__ Wsi, const float* __restrict__ Wsh,
    const float* __restrict__ b_bd, const float* __restrict__ vs,
    const float* __restrict__ Wmx1, const float* __restrict__ Wmh1,
    const float* __restrict__ Wih1, const float* __restrict__ Whh1,
    const float* __restrict__ b1,
    const float* __restrict__ Wmx2, const float* __restrict__ Wmh2,
    const float* __restrict__ Wih2, const float* __restrict__ Whh2,
    const float* __restrict__ b2,
    float* __restrict__ out)
{
    __shared__ float As[2][KC][130];
    __shared__ float Ws[2][KC][68];
    __shared__ float red[8];

    const int blk = blockIdx.x;
    const int tid = threadIdx.x;
    const int gtid = blk * NTHR + tid;
    const int wid = tid >> 5, lane = tid & 31;

    // ================= Prologue P1: states, u/wv/bdvs, embeds =================
    for (int i = gtid; i < Bz * Hz; i += GSTRIDE) {
        g_h1[i] = 0.0f; g_c1[i] = 0.0f; g_h2[i] = 0.0f; g_c2[i] = 0.0f;
    }
    if (blk == 0) {
        for (int f = tid; f < FEATz; f += NTHR) {
            float s = 0.0f;
            for (int m = 0; m < MIDz; m++) s += Wsi[(size_t)m * FEATz + f] * vs[m];
            g_u[f] = s;
        }
        float sb = b_bd[tid] * vs[tid] + b_bd[tid + 256] * vs[tid + 256];
#pragma unroll
        for (int o = 16; o; o >>= 1) sb += __shfl_xor_sync(~0u, sb, o);
        if (lane == 0) red[wid] = sb;
        __syncthreads();
        if (tid == 0) {
            float s = 0.0f;
            for (int w = 0; w < 8; w++) s += red[w];
            g_bdvs = s;
        }
        __syncthreads();
    }
    if (blk == 1) {
        for (int h = tid; h < Hz; h += NTHR) {
            float s = 0.0f;
            for (int m = 0; m < MIDz; m++) s += Wsh[(size_t)m * Hz + h] * vs[m];
            g_wv[h] = s;
        }
    }
    {   // embed gather, float4 granularity (576 = 144 float4)
        const int Q = FEATz / 4;
        for (int i = gtid; i < Sz * Bz * Q; i += GSTRIDE) {
            int q = i % Q;
            int row = i / Q;
            int b = row & (Bz - 1);
            int t = row >> 7;
            int f = q * 4;
            float4 v;
            if (f < 512) v = *(const float4*)(wemb + (size_t)ids[b * Sz + t] * 512 + f);
            else         v = *(const float4*)(xemb + (size_t)xids[b * Sz + t] * 64 + (f - 512));
            *(float4*)(g_embeds + (size_t)row * FEATz + f) = v;
        }
    }
    gridbar();

    // ================= Prologue P2: zbxv + all x-dependent GEMMs ==============
    {   // zbxv[r] = embeds_row · u + bdvs   (one warp per row)
        float bdv = g_bdvs;
        for (int r = blk * 8 + wid; r < Sz * Bz; r += NBLK * 8) {
            const float* e = g_embeds + (size_t)r * FEATz;
            float s = 0.0f;
            for (int j = lane; j < FEATz; j += 32) s += e[j] * g_u[j];
#pragma unroll
            for (int o = 16; o; o >>= 1) s += __shfl_xor_sync(~0u, s, o);
            if (lane == 0) g_zbxv[r] = s + bdv;
        }
    }
    // 512 * (16 + 64) = 40960 GEMM items, K=576
    for (int it = blk; it < 40960; it += NBLK) {
        int t = it / 80, j = it % 80;
        const float* Aa[1] = { g_embeds + (size_t)t * Bz * FEATz };
        if (j < 16)
            gemm_tile<128, 1, 0>(Aa, nullptr, FEATz,
                Wmx1 + (size_t)j * 64 * FEATz, FEATz, FEATz,
                g_mx1all + (size_t)t * Bz * Hz + j * 64, Hz, As, Ws);
        else
            gemm_tile<128, 1, 0>(Aa, nullptr, FEATz,
                Wih1 + (size_t)(j - 16) * 64 * FEATz, FEATz, FEATz,
                g_zx1all + (size_t)t * Bz * G4Hz + (j - 16) * 64, G4Hz, As, Ws);
    }
    gridbar();

    // ============================ time loop ===================================
    for (int t = 0; t < Sz; t++) {

        // ---- Phase A': mh1 partials (64x64 tiles, K split 2) + boundary s ----
        if (blk < 64) {
            int tile = blk >> 2;
            int mh = (blk >> 1) & 1, kh = blk & 1;
            const float* Aa[1] = { g_h1 + (size_t)mh * 64 * Hz + kh * 512 };
            gemm_tile<64, 1, 0>(Aa, nullptr, Hz,
                Wmh1 + (size_t)tile * 64 * Hz + kh * 512, Hz, 512,
                g_mh1p[kh] + (size_t)mh * 64 * Hz + tile * 64, Hz, As, Ws);
        } else if (blk >= 128) {
            // s[r] = (h1_r · wv + zbxv[t,r] > 0)
            for (int r = blk - 128; r < Bz; r += 20) {
                const float* h1r = g_h1 + (size_t)r * Hz;
                float s = h1r[tid]       * g_wv[tid]
                        + h1r[tid + 256] * g_wv[tid + 256]
                        + h1r[tid + 512] * g_wv[tid + 512]
                        + h1r[tid + 768] * g_wv[tid + 768];
#pragma unroll
                for (int o = 16; o; o >>= 1) s += __shfl_xor_sync(~0u, s, o);
                if (lane == 0) red[wid] = s;
                __syncthreads();
                if (tid == 0) {
                    float sum = g_zbxv[t * Bz + r];
                    for (int w = 0; w < 8; w++) sum += red[w];
                    g_s[r] = (sum > 0.0f) ? 1.0f : 0.0f;
                }
                __syncthreads();
            }
        }
        gridbar();

        const float flag = g_s[0];
        const bool doflag = (flag > 0.5f);
        if (blk == 0 && tid == 0) out[OUT_FLAGS + t] = flag;

        // ---- Phase B: p1 = (mx1all[t] .* (mh1p0+mh1p1)) @ Whh1^T ----
        if (blk < 128) {
            int tile = blk >> 1, half = blk & 1, ko = half * 512;
            const float* Aa[1] = { g_mx1all + (size_t)t * Bz * Hz + ko };
            const float* Mp[2] = { g_mh1p[0] + ko, g_mh1p[1] + ko };
            gemm_tile<128, 1, 2>(Aa, Mp, Hz,
                Whh1 + (size_t)tile * 64 * Hz + ko, Hz, 512,
                g_p1p[half] + tile * 64, G4Hz, As, Ws);
        }
        gridbar();

        // ---- Phase C: gates1 (+ output write when flag==0) ----
        {
            const float* zx1 = g_zx1all + (size_t)t * Bz * G4Hz;
            for (int idx = gtid; idx < Bz * Hz; idx += GSTRIDE) {
                int b = idx >> 10, h = idx & (Hz - 1);
                size_t zi = (size_t)b * G4Hz + h;
                float vi = zx1[zi]          + b1[h]          + g_p1p[0][zi]          + g_p1p[1][zi];
                float vf = zx1[zi + Hz]     + b1[h + Hz]     + g_p1p[0][zi + Hz]     + g_p1p[1][zi + Hz];
                float vg = zx1[zi + 2*Hz]   + b1[h + 2*Hz]   + g_p1p[0][zi + 2*Hz]   + g_p1p[1][zi + 2*Hz];
                float vo = zx1[zi + 3*Hz]   + b1[h + 3*Hz]   + g_p1p[0][zi + 3*Hz]   + g_p1p[1][zi + 3*Hz];
                float c  = sigm(vf) * g_c1[idx] + sigm(vi) * tanhf(vg);
                float hn = sigm(vo) * tanhf(c);
                float sv = g_s[b];
                g_x2[idx] = hn * sv;
                g_h1[idx] = hn * (1.0f - sv);
                g_c1[idx] = c  * (1.0f - sv);
                if (!doflag)
                    out[(size_t)b * Sz * Hz + (size_t)t * Hz + h] = g_h2[idx];
            }
        }
        gridbar();   // end of C (end of step when flag==0)

        if (!doflag) continue;   // uniform across all blocks

        // ---- Phase D: mx2, zx2, mh2 (K split 352/336/336): 288 items ----
        for (int it2 = blk; it2 < 288; it2 += NBLK) {
            int tile = it2 / 3, seg = it2 % 3;
            int ko = (seg == 0) ? 0 : (seg == 1 ? 352 : 688);
            int kl = (seg == 0) ? 352 : 336;
            const float* Aa[1];
            if (tile < 16) {
                Aa[0] = g_x2 + ko;
                gemm_tile<128, 1, 0>(Aa, nullptr, Hz,
                    Wmx2 + (size_t)tile * 64 * Hz + ko, Hz, kl,
                    g_mx2p[seg] + tile * 64, Hz, As, Ws);
            } else if (tile < 80) {
                int z = tile - 16;
                Aa[0] = g_x2 + ko;
                gemm_tile<128, 1, 0>(Aa, nullptr, Hz,
                    Wih2 + (size_t)z * 64 * Hz + ko, Hz, kl,
                    g_zx2p[seg] + z * 64, G4Hz, As, Ws);
            } else {
                int m2 = tile - 80;
                Aa[0] = g_h2 + ko;
                gemm_tile<128, 1, 0>(Aa, nullptr, Hz,
                    Wmh2 + (size_t)m2 * 64 * Hz + ko, Hz, kl,
                    g_mh2p[seg] + m2 * 64, Hz, As, Ws);
            }
        }
        gridbar();

        // ---- Phase E: p2 = ((Σmx2p) .* (Σmh2p)) @ Whh2^T ----
        if (blk < 128) {
            int tile = blk >> 1, half = blk & 1, ko = half * 512;
            const float* Aa[3] = { g_mx2p[0] + ko, g_mx2p[1] + ko, g_mx2p[2] + ko };
            const float* Mp[3] = { g_mh2p[0] + ko, g_mh2p[1] + ko, g_mh2p[2] + ko };
            gemm_tile<128, 3, 3>(Aa, Mp, Hz,
                Whh2 + (size_t)tile * 64 * Hz + ko, Hz, 512,
                g_p2p[half] + tile * 64, G4Hz, As, Ws);
        }
        gridbar();

        // ---- Phase F: gates2 + state update + output write ----
        for (int idx = gtid; idx < Bz * Hz; idx += GSTRIDE) {
            int b = idx >> 10, h = idx & (Hz - 1);
            size_t zi = (size_t)b * G4Hz + h;
            float vi = g_zx2p[0][zi]          + g_zx2p[1][zi]          + g_zx2p[2][zi]
                     + b2[h]                  + g_p2p[0][zi]           + g_p2p[1][zi];
            float vf = g_zx2p[0][zi + Hz]     + g_zx2p[1][zi + Hz]     + g_zx2p[2][zi + Hz]
                     + b2[h + Hz]             + g_p2p[0][zi + Hz]      + g_p2p[1][zi + Hz];
            float vg = g_zx2p[0][zi + 2*Hz]   + g_zx2p[1][zi + 2*Hz]   + g_zx2p[2][zi + 2*Hz]
                     + b2[h + 2*Hz]           + g_p2p[0][zi + 2*Hz]    + g_p2p[1][zi + 2*Hz];
            float vo = g_zx2p[0][zi + 3*Hz]   + g_zx2p[1][zi + 3*Hz]   + g_zx2p[2][zi + 3*Hz]
                     + b2[h + 3*Hz]           + g_p2p[0][zi + 3*Hz]    + g_p2p[1][zi + 3*Hz];
            float c  = sigm(vf) * g_c2[idx] + sigm(vi) * tanhf(vg);
            float hn = sigm(vo) * tanhf(c);
            g_c2[idx] = c;
            g_h2[idx] = hn;
            out[(size_t)b * Sz * Hz + (size_t)t * Hz + h] = hn;
        }
        gridbar();
    }

    // ---------------- final state outputs ----------------
    for (int i = gtid; i < Bz * Hz; i += GSTRIDE) {
        out[OUT_H2 + i] = g_h2[i];
        out[OUT_C2 + i] = g_c2[i];
    }
}

// ---------------------------------------------------------------------------
// Launch: ONE kernel node, graph-capturable
// ---------------------------------------------------------------------------
extern "C" void kernel_launch(void* const* d_in, const int* in_sizes, int n_in,
                              void* d_out, int out_size) {
    const int*   ids   = (const int*)d_in[0];
    const int*   xids  = (const int*)d_in[1];
    const float* wemb  = (const float*)d_in[2];
    const float* xemb  = (const float*)d_in[3];
    const float* Wsi   = (const float*)d_in[4];
    const float* Wsh   = (const float*)d_in[5];
    const float* b_bd  = (const float*)d_in[6];
    const float* vs    = (const float*)d_in[7];
    const float* Wmx1  = (const float*)d_in[8];
    const float* Wmh1  = (const float*)d_in[9];
    const float* Wih1  = (const float*)d_in[10];
    const float* Whh1  = (const float*)d_in[11];
    const float* b1    = (const float*)d_in[12];
    const float* Wmx2  = (const float*)d_in[13];
    const float* Wmh2  = (const float*)d_in[14];
    const float* Wih2  = (const float*)d_in[15];
    const float* Whh2  = (const float*)d_in[16];
    const float* b2    = (const float*)d_in[17];
    float* out = (float*)d_out;

    enc_persistent<<<NBLK, NTHR>>>(ids, xids, wemb, xemb,
                                   Wsi, Wsh, b_bd, vs,
                                   Wmx1, Wmh1, Wih1, Whh1, b1,
                                   Wmx2, Wmh2, Wih2, Whh2, b2,
                                   out);
}